// round 1
// baseline (speedup 1.0000x reference)
#include <cuda_runtime.h>
#include <cuda_bf16.h>

// CostVolumn: out[b, dy*9+dx, y, x] = leaky( mean_c( c1[b,c,y,x] * warped_pad[b,c,y+dy-4, x+dx-4] ) )
// Shapes: c1/warped (8,192,128,160) f32, out (8,81,128,160) f32, alpha scalar.

namespace {
constexpr int B_ = 8;
constexpr int C_ = 192;
constexpr int H_ = 128;
constexpr int W_ = 160;
constexpr int SR = 4;          // search range
constexpr int MO = 9;          // 2*SR+1 offsets per dim
constexpr int TH = 8;          // tile rows
constexpr int TW = 32;         // tile cols
constexpr int CC = 8;          // channels per smem chunk
constexpr int HALO_H = TH + 2 * SR;  // 16
constexpr int HALO_W = TW + 2 * SR;  // 40
constexpr int NTHREADS = 8 * 8 * 9;  // 576
}

__global__ __launch_bounds__(NTHREADS, 1)
void costvol_kernel(const float* __restrict__ c1,
                    const float* __restrict__ warped,
                    const float* __restrict__ alpha,
                    float* __restrict__ out) {
    __shared__ float s_c1[CC][TH][TW];           // 8 KB
    __shared__ float s_w[CC][HALO_H][HALO_W];    // 20 KB

    const int q  = threadIdx.x;   // x-quad, 0..7  (covers x = 4q..4q+3)
    const int ly = threadIdx.y;   // tile row, 0..7
    const int dz = threadIdx.z;   // dy offset index, 0..8
    const int tid = q + 8 * (ly + 8 * dz);

    const int x0 = blockIdx.x * TW;   // gridDim.x = W/TW = 5
    const int y0 = blockIdx.y * TH;   // gridDim.y = H/TH = 16
    const int b  = blockIdx.z;        // gridDim.z = 8

    const float* __restrict__ c1b = c1 + (size_t)b * C_ * H_ * W_;
    const float* __restrict__ wb  = warped + (size_t)b * C_ * H_ * W_;

    float acc[MO][4];
#pragma unroll
    for (int dx = 0; dx < MO; dx++)
#pragma unroll
        for (int xi = 0; xi < 4; xi++) acc[dx][xi] = 0.f;

    for (int c0 = 0; c0 < C_; c0 += CC) {
        __syncthreads();  // protect smem from previous iteration's readers

        // ---- stage c1 tile: CC*TH*TW = 2048 floats ----
#pragma unroll
        for (int i = tid; i < CC * TH * TW; i += NTHREADS) {
            int cc = i / (TH * TW);
            int r  = i % (TH * TW);
            int yy = r / TW;
            int xx = r % TW;
            s_c1[cc][yy][xx] = c1b[(size_t)(c0 + cc) * (H_ * W_) + (y0 + yy) * W_ + (x0 + xx)];
        }
        // ---- stage warped halo: CC*16*40 = 5120 floats (zero-pad OOB) ----
#pragma unroll
        for (int i = tid; i < CC * HALO_H * HALO_W; i += NTHREADS) {
            int cc = i / (HALO_H * HALO_W);
            int r  = i % (HALO_H * HALO_W);
            int hy = r / HALO_W;
            int hx = r % HALO_W;
            int gy = y0 + hy - SR;
            int gx = x0 + hx - SR;
            float v = 0.f;
            if ((unsigned)gy < (unsigned)H_ && (unsigned)gx < (unsigned)W_)
                v = wb[(size_t)(c0 + cc) * (H_ * W_) + gy * W_ + gx];
            s_w[cc][hy][hx] = v;
        }
        __syncthreads();

        // ---- accumulate: per channel, 16 LDS floats -> 36 FFMAs ----
#pragma unroll
        for (int cc = 0; cc < CC; cc++) {
            float4 a4 = *reinterpret_cast<const float4*>(&s_c1[cc][ly][q * 4]);
            float a[4] = {a4.x, a4.y, a4.z, a4.w};

            const float* wrow = &s_w[cc][ly + dz][q * 4];
            float4 w0 = *reinterpret_cast<const float4*>(wrow);
            float4 w1 = *reinterpret_cast<const float4*>(wrow + 4);
            float4 w2 = *reinterpret_cast<const float4*>(wrow + 8);
            float wv[12] = {w0.x, w0.y, w0.z, w0.w,
                            w1.x, w1.y, w1.z, w1.w,
                            w2.x, w2.y, w2.z, w2.w};
#pragma unroll
            for (int dx = 0; dx < MO; dx++)
#pragma unroll
                for (int xi = 0; xi < 4; xi++)
                    acc[dx][xi] = fmaf(a[xi], wv[xi + dx], acc[dx][xi]);
        }
    }

    // ---- epilogue: mean + leaky, float4 stores ----
    const float al = __ldg(alpha);
    const float inv = 1.0f / (float)C_;
    const int gy = y0 + ly;
    const int gxbase = x0 + q * 4;

#pragma unroll
    for (int dx = 0; dx < MO; dx++) {
        int o = dz * MO + dx;
        float4 v;
        float t;
        t = acc[dx][0] * inv; v.x = (t >= 0.f) ? t : al * t;
        t = acc[dx][1] * inv; v.y = (t >= 0.f) ? t : al * t;
        t = acc[dx][2] * inv; v.z = (t >= 0.f) ? t : al * t;
        t = acc[dx][3] * inv; v.w = (t >= 0.f) ? t : al * t;
        float* dst = out + ((size_t)(b * 81 + o) * H_ + gy) * W_ + gxbase;
        *reinterpret_cast<float4*>(dst) = v;
    }
}

extern "C" void kernel_launch(void* const* d_in, const int* in_sizes, int n_in,
                              void* d_out, int out_size) {
    const float* c1     = (const float*)d_in[0];
    const float* warped = (const float*)d_in[1];
    const float* alpha  = (const float*)d_in[2];
    float* out = (float*)d_out;

    dim3 block(8, 8, 9);                 // 576 threads
    dim3 grid(W_ / TW, H_ / TH, B_);     // (5, 16, 8)
    costvol_kernel<<<grid, block>>>(c1, warped, alpha, out);
}

// round 2
// speedup vs baseline: 3.4142x; 3.4142x over previous
#include <cuda_runtime.h>
#include <cuda_bf16.h>
#include <cstdint>

// CostVolumn: out[b, dy*9+dx, y, x] = leaky( mean_c( c1[b,c,y,x] * warped_pad[b,c,y+dy-4, x+dx-4] ) )
// Shapes: c1/warped (8,192,128,160) f32, out (8,81,128,160) f32, alpha scalar.

namespace {
constexpr int B_ = 8;
constexpr int C_ = 192;
constexpr int H_ = 128;
constexpr int W_ = 160;
constexpr int SR = 4;
constexpr int MO = 9;
constexpr int TH = 8;
constexpr int TW = 32;
constexpr int CC = 16;                 // channels per stage
constexpr int NCH = C_ / CC;           // 12 chunks
constexpr int HALO_H = TH + 2 * SR;    // 16
constexpr int HALO_W = TW + 2 * SR;    // 40
constexpr int NTHREADS = 8 * 8 * 9;    // 576
constexpr int HW = H_ * W_;

constexpr int SW_ELEMS = CC * HALO_H * HALO_W;  // 10240 floats (warped halo)
constexpr int SC_ELEMS = CC * TH * TW;          // 4096 floats  (c1 tile)
constexpr int STAGE = SW_ELEMS + SC_ELEMS;      // 14336 floats per stage
constexpr int SMEM_BYTES = 2 * STAGE * 4;       // 114688 B

// 16B staging units
constexpr int UW = CC * HALO_H * (HALO_W / 4);  // 2560 units (10 per halo row)
constexpr int UC = CC * TH * (TW / 4);          // 1024 units
constexpr int UTOT = UW + UC;                   // 3584
constexpr int SLOTS = (UTOT + NTHREADS - 1) / NTHREADS;  // 7
}

__global__ __launch_bounds__(NTHREADS, 1)
void costvol_kernel(const float* __restrict__ c1,
                    const float* __restrict__ warped,
                    const float* __restrict__ alpha,
                    float* __restrict__ out) {
    extern __shared__ float smem[];

    const int q  = threadIdx.x;   // x-quad 0..7
    const int ly = threadIdx.y;   // tile row 0..7
    const int dz = threadIdx.z;   // dy index 0..8
    const int tid = q + 8 * (ly + 8 * dz);

    const int x0 = blockIdx.x * TW;
    const int y0 = blockIdx.y * TH;
    const int b  = blockIdx.z;

    const float* __restrict__ c1b = c1 + (size_t)b * C_ * HW;
    const float* __restrict__ wb  = warped + (size_t)b * C_ * HW;

    // ---- precompute per-thread staging slots (geometry fixed across chunks) ----
    uint32_t soff[SLOTS];   // byte offset within a stage
    int32_t  goff[SLOTS];   // float offset within a channel-chunk
    bool     valid[SLOTS];
    bool     isw[SLOTS];
#pragma unroll
    for (int s = 0; s < SLOTS; s++) {
        valid[s] = false; isw[s] = false; soff[s] = 0; goff[s] = 0;
        int i = tid + NTHREADS * s;
        if (i < UW) {
            int cc = i / (HALO_H * 10);
            int rem = i % (HALO_H * 10);
            int hy = rem / 10;
            int seg = rem % 10;
            int gy = y0 + hy - SR;
            int gx = x0 - SR + seg * 4;
            isw[s] = true;
            soff[s] = (uint32_t)(cc * HALO_H * HALO_W + hy * HALO_W + seg * 4) * 4u;
            goff[s] = cc * HW + gy * W_ + gx;
            valid[s] = (gy >= 0) && (gy < H_) && (gx >= 0) && (gx + 4 <= W_);
        } else if (i < UTOT) {
            int j = i - UW;
            int cc = j / (TH * 8);
            int rem = j % (TH * 8);
            int yy = rem / 8;
            int seg = rem % 8;
            soff[s] = (uint32_t)(SW_ELEMS + cc * TH * TW + yy * TW + seg * 4) * 4u;
            goff[s] = cc * HW + (y0 + yy) * W_ + (x0 + seg * 4);
            valid[s] = true;
        }
    }

    // ---- zero warped halo regions once (border padding persists; cp.async never touches OOB slots) ----
    for (int i = tid; i < SW_ELEMS; i += NTHREADS) {
        smem[i] = 0.f;
        smem[STAGE + i] = 0.f;
    }
    __syncthreads();

    const uint32_t smem_u32 = (uint32_t)__cvta_generic_to_shared(smem);

    auto issue_stage = [&](int k) {
        const uint32_t sbase = smem_u32 + (uint32_t)((k & 1) * STAGE) * 4u;
        const size_t coff = (size_t)(k * CC) * HW;
#pragma unroll
        for (int s = 0; s < SLOTS; s++) {
            if (valid[s]) {
                const float* g = (isw[s] ? wb : c1b) + coff + goff[s];
                uint32_t sa = sbase + soff[s];
                asm volatile("cp.async.cg.shared.global [%0], [%1], 16;"
                             :: "r"(sa), "l"(g) : "memory");
            }
        }
        asm volatile("cp.async.commit_group;" ::: "memory");
    };

    // prologue: 2 stages in flight
    issue_stage(0);
    issue_stage(1);

    float acc[MO][4];
#pragma unroll
    for (int dx = 0; dx < MO; dx++)
#pragma unroll
        for (int xi = 0; xi < 4; xi++) acc[dx][xi] = 0.f;

    for (int k = 0; k < NCH; k++) {
        if (k + 1 < NCH) {
            asm volatile("cp.async.wait_group 1;" ::: "memory");
        } else {
            asm volatile("cp.async.wait_group 0;" ::: "memory");
        }
        __syncthreads();   // stage k visible to all

        const float* ws = smem + (k & 1) * STAGE;
        const float* cs = ws + SW_ELEMS;

#pragma unroll
        for (int cc = 0; cc < CC; cc++) {
            float4 a4 = *reinterpret_cast<const float4*>(cs + cc * (TH * TW) + ly * TW + q * 4);
            float a[4] = {a4.x, a4.y, a4.z, a4.w};

            const float* wrow = ws + cc * (HALO_H * HALO_W) + (ly + dz) * HALO_W + q * 4;
            float4 w0 = *reinterpret_cast<const float4*>(wrow);
            float4 w1 = *reinterpret_cast<const float4*>(wrow + 4);
            float4 w2 = *reinterpret_cast<const float4*>(wrow + 8);
            float wv[12] = {w0.x, w0.y, w0.z, w0.w,
                            w1.x, w1.y, w1.z, w1.w,
                            w2.x, w2.y, w2.z, w2.w};
#pragma unroll
            for (int dx = 0; dx < MO; dx++)
#pragma unroll
                for (int xi = 0; xi < 4; xi++)
                    acc[dx][xi] = fmaf(a[xi], wv[xi + dx], acc[dx][xi]);
        }

        __syncthreads();   // all threads done reading buf (k&1)
        if (k + 2 < NCH) issue_stage(k + 2);
    }

    // ---- epilogue: mean + leaky, float4 stores ----
    const float al = __ldg(alpha);
    const float inv = 1.0f / (float)C_;
    const int gy = y0 + ly;
    const int gxbase = x0 + q * 4;

#pragma unroll
    for (int dx = 0; dx < MO; dx++) {
        int o = dz * MO + dx;
        float4 v;
        float t;
        t = acc[dx][0] * inv; v.x = (t >= 0.f) ? t : al * t;
        t = acc[dx][1] * inv; v.y = (t >= 0.f) ? t : al * t;
        t = acc[dx][2] * inv; v.z = (t >= 0.f) ? t : al * t;
        t = acc[dx][3] * inv; v.w = (t >= 0.f) ? t : al * t;
        float* dst = out + ((size_t)(b * 81 + o) * H_ + gy) * W_ + gxbase;
        *reinterpret_cast<float4*>(dst) = v;
    }
}

extern "C" void kernel_launch(void* const* d_in, const int* in_sizes, int n_in,
                              void* d_out, int out_size) {
    const float* c1     = (const float*)d_in[0];
    const float* warped = (const float*)d_in[1];
    const float* alpha  = (const float*)d_in[2];
    float* out = (float*)d_out;

    cudaFuncSetAttribute(costvol_kernel,
                         cudaFuncAttributeMaxDynamicSharedMemorySize, SMEM_BYTES);

    dim3 block(8, 8, 9);              // 576
    dim3 grid(W_ / TW, H_ / TH, B_);  // (5, 16, 8)
    costvol_kernel<<<grid, block, SMEM_BYTES>>>(c1, warped, alpha, out);
}